// round 4
// baseline (speedup 1.0000x reference)
#include <cuda_runtime.h>
#include <cstdint>

// DepthEmissionRaymarcher: B=2,H=192,W=320,P=128,F=8
// One warp per ray. Warp-scan cumsum of densities (wall=1 on last point),
// clamp to 1, diff -> absorption probs. depth = sum(probs*len),
// features = sum(probs * feat).
// HBM-bound (~629 MB read @ 7.0 TB/s). R3: split feature loads into two
// batches of 4 around the scan to cut peak live regs (48 -> ~40) and
// recover occupancy (5 -> 6 blocks/SM) while keeping MLP high.

static constexpr int P = 128;
static constexpr int F = 8;
static constexpr int WARPS_PER_BLOCK = 8;
static constexpr int THREADS = WARPS_PER_BLOCK * 32;

__global__ __launch_bounds__(THREADS)
void raymarch_kernel(const float* __restrict__ dens,
                     const float* __restrict__ feat,
                     const float* __restrict__ len,
                     float* __restrict__ depth_out,
                     float* __restrict__ feat_out,
                     int R)
{
    __shared__ float sprobs[WARPS_PER_BLOCK][P];

    const int lane = threadIdx.x & 31;
    const int warp_in_block = threadIdx.x >> 5;
    const int ray = blockIdx.x * WARPS_PER_BLOCK + warp_in_block;
    if (ray >= R) return;  // whole warp exits together

    // ---- batch 1: dens + len + first 4 feature vectors (6 LDG.128) ----
    const float4 d4 = __ldcs(reinterpret_cast<const float4*>(dens + (size_t)ray * P) + lane);
    const float4 l4 = __ldcs(reinterpret_cast<const float4*>(len  + (size_t)ray * P) + lane);
    const float4* fv = reinterpret_cast<const float4*>(feat + (size_t)ray * P * F);
    float4 f0 = __ldcs(fv + lane +  0);
    float4 f1 = __ldcs(fv + lane + 32);
    float4 f2 = __ldcs(fv + lane + 64);
    float4 f3 = __ldcs(fv + lane + 96);

    // ---- density scan (wall=1 on last point) — covers load latency ----
    float dd0 = d4.x, dd1 = d4.y, dd2 = d4.z, dd3 = d4.w;
    if (lane == 31) dd3 = 1.0f;

    const float s0 = dd0;
    const float s1 = s0 + dd1;
    const float s2 = s1 + dd2;
    const float s3 = s2 + dd3;

    float incl = s3;
    #pragma unroll
    for (int off = 1; off < 32; off <<= 1) {
        float v = __shfl_up_sync(0xffffffffu, incl, off);
        if (lane >= off) incl += v;
    }
    const float excl = incl - s3;

    const float cprev = fminf(excl, 1.0f);
    const float c0 = fminf(excl + s0, 1.0f);
    const float c1 = fminf(excl + s1, 1.0f);
    const float c2 = fminf(excl + s2, 1.0f);
    const float c3 = fminf(excl + s3, 1.0f);
    const float p0 = c0 - cprev;
    const float p1 = c1 - c0;
    const float p2 = c2 - c1;
    const float p3 = c3 - c2;

    // stash probs for the feature-weight gather
    sprobs[warp_in_block][lane * 4 + 0] = p0;
    sprobs[warp_in_block][lane * 4 + 1] = p1;
    sprobs[warp_in_block][lane * 4 + 2] = p2;
    sprobs[warp_in_block][lane * 4 + 3] = p3;

    // ---- batch 2: remaining 4 feature vectors ----
    float4 f4 = __ldcs(fv + lane + 128);
    float4 f5 = __ldcs(fv + lane + 160);
    float4 f6 = __ldcs(fv + lane + 192);
    float4 f7 = __ldcs(fv + lane + 224);

    // ---- depth: probs . lengths ----
    float dpart = p0 * l4.x + p1 * l4.y + p2 * l4.z + p3 * l4.w;
    #pragma unroll
    for (int off = 16; off > 0; off >>= 1)
        dpart += __shfl_xor_sync(0xffffffffu, dpart, off);
    if (lane == 0) __stcs(depth_out + ray, dpart);

    __syncwarp();

    // ---- features: float4 index k = lane + 32*j -> point k>>1, half k&1.
    // Parity of k == parity of lane: even lanes accumulate feats[0:4],
    // odd lanes feats[4:8].
    float a0, a1, a2, a3;
    {
        const float pw = sprobs[warp_in_block][(lane + 0) >> 1];
        a0 = pw * f0.x; a1 = pw * f0.y; a2 = pw * f0.z; a3 = pw * f0.w;
    }
    #define ACC(FJ, KOFF)  do {                                        \
        const float pw = sprobs[warp_in_block][(lane + (KOFF)) >> 1];  \
        a0 += pw * FJ.x; a1 += pw * FJ.y;                              \
        a2 += pw * FJ.z; a3 += pw * FJ.w; } while (0)
    ACC(f1, 32); ACC(f2, 64); ACC(f3, 96);
    ACC(f4, 128); ACC(f5, 160); ACC(f6, 192); ACC(f7, 224);
    #undef ACC

    #pragma unroll
    for (int off = 16; off >= 2; off >>= 1) {
        a0 += __shfl_xor_sync(0xffffffffu, a0, off);
        a1 += __shfl_xor_sync(0xffffffffu, a1, off);
        a2 += __shfl_xor_sync(0xffffffffu, a2, off);
        a3 += __shfl_xor_sync(0xffffffffu, a3, off);
    }
    if (lane < 2) {
        float4 outv = make_float4(a0, a1, a2, a3);
        __stcs(reinterpret_cast<float4*>(feat_out + (size_t)ray * F) + lane, outv);
    }
}

extern "C" void kernel_launch(void* const* d_in, const int* in_sizes, int n_in,
                              void* d_out, int out_size)
{
    const float* dens = (const float*)d_in[0];  // (B,H,W,P,1)
    const float* feat = (const float*)d_in[1];  // (B,H,W,P,F)
    const float* len  = (const float*)d_in[2];  // (B,H,W,P)

    const int R = in_sizes[2] / P;              // number of rays

    float* depth_out = (float*)d_out;           // (B,H,W) flattened
    float* feat_out  = depth_out + R;           // (B,H,W,F) flattened

    const int blocks = (R + WARPS_PER_BLOCK - 1) / WARPS_PER_BLOCK;
    raymarch_kernel<<<blocks, THREADS>>>(dens, feat, len, depth_out, feat_out, R);
}

// round 7
// speedup vs baseline: 4.4214x; 4.4214x over previous
#include <cuda_runtime.h>
#include <cstdint>

// DepthEmissionRaymarcher: B=2,H=192,W=320,P=128,F=8
// R4/R5: early-termination raymarch. probs = diff(min(cumsum(d),1)) are EXACTLY
// zero once the clamped cumsum reaches 1.0, so we only read densities/lengths/
// features up to the saturation point (E[sat] = e ~ 2.7 points for uniform[0,1]
// densities). Chunked 32-point loop handles the general (non-saturating) case
// including the wall at point 127. Traffic: ~629MB -> ~52MB.
// (R5 = R4 resubmit: previous bench was an infra failure, kernel never ran.)

static constexpr int P = 128;
static constexpr int F = 8;
static constexpr int WARPS_PER_BLOCK = 8;
static constexpr int THREADS = WARPS_PER_BLOCK * 32;

__global__ __launch_bounds__(THREADS)
void raymarch_kernel(const float* __restrict__ dens,
                     const float* __restrict__ feat,
                     const float* __restrict__ len,
                     float* __restrict__ depth_out,
                     float* __restrict__ feat_out,
                     int R)
{
    __shared__ float sprob[WARPS_PER_BLOCK][32];

    const int lane = threadIdx.x & 31;
    const int w = threadIdx.x >> 5;
    const int ray = blockIdx.x * WARPS_PER_BLOCK + w;
    if (ray >= R) return;  // whole warp exits together

    const float* draw = dens + (size_t)ray * P;
    const float* lraw = len  + (size_t)ray * P;
    const float* fraw = feat + (size_t)ray * P * F;

    const int fpt = lane >> 3;   // point-in-batch 0..3
    const int ff  = lane & 7;    // feature index 0..7

    float base  = 0.0f;          // raw (unclamped) cumsum before this chunk
    float depth = 0.0f;
    float a     = 0.0f;          // per-lane feature partial (class = lane&7)

    #pragma unroll 1
    for (int c = 0; c < P / 32; ++c) {
        const int p0 = c * 32;

        // coalesced 128B loads: dens chunk, len chunk, feature batch 0
        float d  = __ldcs(draw + p0 + lane);
        float lv = __ldcs(lraw + p0 + lane);
        float f0 = __ldcs(fraw + (size_t)(p0 + fpt) * F + ff);

        if (c == (P / 32 - 1) && lane == 31) d = 1.0f;  // wall=True

        // warp inclusive scan of raw densities within chunk
        float inc = d;
        #pragma unroll
        for (int off = 1; off < 32; off <<= 1) {
            float v = __shfl_up_sync(0xffffffffu, inc, off);
            if (lane >= off) inc += v;
        }
        float prev = __shfl_up_sync(0xffffffffu, inc, 1);
        if (lane == 0) prev = 0.0f;

        const float ck   = fminf(base + inc,  1.0f);
        const float ckm1 = fminf(base + prev, 1.0f);
        const float prob = ck - ckm1;   // exactly 0 beyond saturation

        depth += prob * lv;

        sprob[w][lane] = prob;
        const unsigned satmask = __ballot_sync(0xffffffffu, ck >= 1.0f);
        const int n_active = satmask ? __ffs(satmask) : 32;  // points with possibly nonzero prob
        __syncwarp();

        // feature batch 0 (points p0..p0+3): always needed
        a += sprob[w][fpt] * f0;

        // further batches only while points may carry weight (n_active is
        // warp-uniform, so no divergence)
        for (int b = 4; b < n_active; b += 4) {
            float fv = __ldcs(fraw + (size_t)(p0 + b + fpt) * F + ff);
            a += sprob[w][b + fpt] * fv;
        }
        __syncwarp();  // protect sprob before next chunk overwrites

        if (satmask) break;           // all later probs exactly zero
        base += __shfl_sync(0xffffffffu, inc, 31);
    }

    // depth: full warp reduce
    #pragma unroll
    for (int off = 16; off > 0; off >>= 1)
        depth += __shfl_xor_sync(0xffffffffu, depth, off);
    if (lane == 0) depth_out[ray] = depth;

    // features: combine the 4 point-groups, preserving feature index (lane&7)
    a += __shfl_xor_sync(0xffffffffu, a, 16);
    a += __shfl_xor_sync(0xffffffffu, a, 8);
    if (lane < F) feat_out[(size_t)ray * F + lane] = a;
}

extern "C" void kernel_launch(void* const* d_in, const int* in_sizes, int n_in,
                              void* d_out, int out_size)
{
    const float* dens = (const float*)d_in[0];  // (B,H,W,P,1)
    const float* feat = (const float*)d_in[1];  // (B,H,W,P,F)
    const float* len  = (const float*)d_in[2];  // (B,H,W,P)

    const int R = in_sizes[2] / P;              // number of rays

    float* depth_out = (float*)d_out;           // (B,H,W) flattened
    float* feat_out  = depth_out + R;           // (B,H,W,F) flattened

    const int blocks = (R + WARPS_PER_BLOCK - 1) / WARPS_PER_BLOCK;
    raymarch_kernel<<<blocks, THREADS>>>(dens, feat, len, depth_out, feat_out, R);
}

// round 8
// speedup vs baseline: 8.6190x; 1.9494x over previous
#include <cuda_runtime.h>
#include <cstdint>

// DepthEmissionRaymarcher: B=2,H=192,W=320,P=128,F=8
// R7: 4 rays/warp, 8-lane groups. Probs = diff(min(cumsum(d),1)) are exactly 0
// after saturation (E[sat]~2.7 points), so each group scans 8 points per chunk
// (3 shfl rounds) and nearly always finishes in one chunk. Rare unsaturated
// groups loop further (wall=1 at point 127 guarantees termination).
// First 4 feature loads issued speculatively (addresses independent of probs).

static constexpr int P = 128;
static constexpr int F = 8;
static constexpr int WARPS_PER_BLOCK = 8;
static constexpr int THREADS = WARPS_PER_BLOCK * 32;
static constexpr int RAYS_PER_WARP = 4;

__global__ __launch_bounds__(THREADS)
void raymarch_kernel(const float* __restrict__ dens,
                     const float* __restrict__ feat,
                     const float* __restrict__ len,
                     float* __restrict__ depth_out,
                     float* __restrict__ feat_out,
                     int R)
{
    const int lane = threadIdx.x & 31;
    const int warp = threadIdx.x >> 5;
    const int g    = lane >> 3;      // ray-group within warp (0..3)
    const int sg   = lane & 7;       // sub-lane: point offset / feature index
    const int gbase = lane & 24;     // first lane of this group

    const int warp_ray0 = (blockIdx.x * WARPS_PER_BLOCK + warp) * RAYS_PER_WARP;
    if (warp_ray0 >= R) return;      // warp-uniform exit

    int ray = warp_ray0 + g;
    const bool valid = ray < R;
    if (!valid) ray = R - 1;         // safe addresses; writes predicated on valid

    const float* draw = dens + (size_t)ray * P;
    const float* lraw = len  + (size_t)ray * P;
    const float* fraw = feat + (size_t)ray * P * F;

    float base  = 0.0f;   // raw cumsum before current chunk
    float depth = 0.0f;
    float a     = 0.0f;   // feature partial for feature index sg
    bool  sat   = false;

    #pragma unroll 1
    for (int p0 = 0; p0 < P; p0 += 8) {
        // ---- issue all independent loads up front (MLP=6/lane) ----
        float d  = __ldcs(draw + p0 + sg);
        float lv = __ldcs(lraw + p0 + sg);
        // speculative feature loads for points p0..p0+3 (lane sg = feat idx)
        float f0 = __ldcs(fraw + (size_t)(p0 + 0) * F + sg);
        float f1 = __ldcs(fraw + (size_t)(p0 + 1) * F + sg);
        float f2 = __ldcs(fraw + (size_t)(p0 + 2) * F + sg);
        float f3 = __ldcs(fraw + (size_t)(p0 + 3) * F + sg);

        if (p0 + sg == P - 1) d = 1.0f;   // wall=True on furthest sample

        // ---- 8-wide inclusive scan within group ----
        float inc = d;
        #pragma unroll
        for (int off = 1; off < 8; off <<= 1) {
            float v = __shfl_up_sync(0xffffffffu, inc, off, 8);
            if (sg >= off) inc += v;
        }
        float prev = __shfl_up_sync(0xffffffffu, inc, 1, 8);
        if (sg == 0) prev = 0.0f;

        const float ck   = fminf(base + inc,  1.0f);
        const float ckm1 = fminf(base + prev, 1.0f);
        const float prob = ck - ckm1;     // exactly 0 beyond saturation

        depth += prob * lv;

        // per-group saturation; n_active = first saturated local index + 1
        const unsigned m  = __ballot_sync(0xffffffffu, ck >= 1.0f);
        const unsigned gb = (m >> (g * 8)) & 0xFFu;
        const int nact = gb ? (int)__ffs(gb) : 8;

        // warp-max of nact (value is group-uniform -> xor across groups)
        int nmax = nact;
        nmax = max(nmax, __shfl_xor_sync(0xffffffffu, nmax, 8));
        nmax = max(nmax, __shfl_xor_sync(0xffffffffu, nmax, 16));

        // ---- features: broadcast prob of point i from lane gbase|i ----
        {
            float pw0 = __shfl_sync(0xffffffffu, prob, gbase | 0);
            float pw1 = __shfl_sync(0xffffffffu, prob, gbase | 1);
            float pw2 = __shfl_sync(0xffffffffu, prob, gbase | 2);
            float pw3 = __shfl_sync(0xffffffffu, prob, gbase | 3);
            a += pw0 * f0 + pw1 * f1 + pw2 * f2 + pw3 * f3;
        }
        for (int i = 4; i < nmax; i++) {
            float pw = __shfl_sync(0xffffffffu, prob, gbase | i);
            float fv = __ldcs(fraw + (size_t)(p0 + i) * F + sg);
            a += pw * fv;
        }

        sat = sat || (gb != 0);
        if (__all_sync(0xffffffffu, sat)) break;   // all groups done
        base += __shfl_sync(0xffffffffu, inc, gbase | 7);  // carry raw cumsum
    }

    // ---- depth: reduce over the 8 lanes of the group ----
    #pragma unroll
    for (int off = 4; off > 0; off >>= 1)
        depth += __shfl_xor_sync(0xffffffffu, depth, off);
    if (valid && sg == 0) depth_out[ray] = depth;

    // ---- features: lane -> feat_out[ray*8+sg]; coalesced across warp ----
    if (valid) feat_out[(size_t)ray * F + sg] = a;
}

extern "C" void kernel_launch(void* const* d_in, const int* in_sizes, int n_in,
                              void* d_out, int out_size)
{
    const float* dens = (const float*)d_in[0];  // (B,H,W,P,1)
    const float* feat = (const float*)d_in[1];  // (B,H,W,P,F)
    const float* len  = (const float*)d_in[2];  // (B,H,W,P)

    const int R = in_sizes[2] / P;              // number of rays

    float* depth_out = (float*)d_out;           // (B,H,W) flattened
    float* feat_out  = depth_out + R;           // (B,H,W,F) flattened

    const int rays_per_block = WARPS_PER_BLOCK * RAYS_PER_WARP;
    const int blocks = (R + rays_per_block - 1) / rays_per_block;
    raymarch_kernel<<<blocks, THREADS>>>(dens, feat, len, depth_out, feat_out, R);
}

// round 11
// speedup vs baseline: 8.6448x; 1.0030x over previous
#include <cuda_runtime.h>
#include <cstdint>

// DepthEmissionRaymarcher: B=2,H=192,W=320,P=128,F=8
// R8: 8 rays/warp, 4-lane groups, 2 points per lane (float2 everywhere).
// Chunk = 8 points: pair-sum + 2-round shfl scan. P(ray needs >8 pts) = 1/8!
// ~ 2.5e-5, so effectively one chunk per warp while serving 8 rays.
// Features: speculative float2 loads for pts 0-3 (96% of rays), uniform-branch
// extension for pts 4-7 (~29% of warps). Post-saturation probs are exactly 0,
// so all skipping/unconditional adds are bit-exact.

static constexpr int P = 128;
static constexpr int F = 8;
static constexpr int WARPS_PER_BLOCK = 8;
static constexpr int THREADS = WARPS_PER_BLOCK * 32;
static constexpr int RAYS_PER_WARP = 8;

__global__ __launch_bounds__(THREADS)
void raymarch_kernel(const float* __restrict__ dens,
                     const float* __restrict__ feat,
                     const float* __restrict__ len,
                     float* __restrict__ depth_out,
                     float* __restrict__ feat_out,
                     int R)
{
    const unsigned FULL = 0xffffffffu;
    const int lane = threadIdx.x & 31;
    const int warp = threadIdx.x >> 5;
    const int g  = lane >> 2;        // ray-group within warp (0..7)
    const int sg = lane & 3;         // sub-lane: covers points 2sg, 2sg+1

    const int warp_ray0 = (blockIdx.x * WARPS_PER_BLOCK + warp) * RAYS_PER_WARP;
    if (warp_ray0 >= R) return;      // warp-uniform exit

    int ray = warp_ray0 + g;
    const bool valid = ray < R;
    if (!valid) ray = R - 1;         // safe addresses; writes predicated

    const float* draw = dens + (size_t)ray * P;
    const float* lraw = len  + (size_t)ray * P;
    const float* fraw = feat + (size_t)ray * P * F;

    float base = 0.0f;               // raw cumsum before current chunk
    float depth = 0.0f;
    float acc0 = 0.0f, acc1 = 0.0f;  // feature accum: indices 2sg, 2sg+1

    #pragma unroll 1
    for (int p0 = 0; p0 < P; p0 += 8) {
        const int pl = p0 + 2 * sg;  // this lane's first point

        // ---- front-batched float2 loads (all independent) ----
        float2 d2 = __ldcs(reinterpret_cast<const float2*>(draw + pl));
        float2 l2 = __ldcs(reinterpret_cast<const float2*>(lraw + pl));
        // speculative features: points p0..p0+3, feats 2sg..2sg+1
        float2 f0 = __ldcs(reinterpret_cast<const float2*>(fraw + (p0 + 0) * F + 2 * sg));
        float2 f1 = __ldcs(reinterpret_cast<const float2*>(fraw + (p0 + 1) * F + 2 * sg));
        float2 f2 = __ldcs(reinterpret_cast<const float2*>(fraw + (p0 + 2) * F + 2 * sg));
        float2 f3 = __ldcs(reinterpret_cast<const float2*>(fraw + (p0 + 3) * F + 2 * sg));

        if (pl + 1 == P - 1) d2.y = 1.0f;   // wall=True on furthest sample

        // ---- scan: pair-sum then 2-round inclusive scan over 4 lanes ----
        const float s = d2.x + d2.y;
        float inc = s;
        {
            float v = __shfl_up_sync(FULL, inc, 1, 4);
            if (sg >= 1) inc += v;
            v = __shfl_up_sync(FULL, inc, 2, 4);
            if (sg >= 2) inc += v;
        }
        const float b    = base + (inc - s);      // cumsum before this lane's pts
        const float ckm1 = fminf(b, 1.0f);
        const float ck0  = fminf(b + d2.x, 1.0f);
        const float ck1  = fminf(b + s, 1.0f);
        const float pr0  = ck0 - ckm1;            // exactly 0 past saturation
        const float pr1  = ck1 - ck0;

        depth += pr0 * l2.x + pr1 * l2.y;

        const unsigned mb = __ballot_sync(FULL, ck1 >= 1.0f);

        // ---- features pts 0..3: broadcast probs from lanes 0,1 of group ----
        const float pw0 = __shfl_sync(FULL, pr0, 0, 4);
        const float pw1 = __shfl_sync(FULL, pr1, 0, 4);
        const float pw2 = __shfl_sync(FULL, pr0, 1, 4);
        const float pw3 = __shfl_sync(FULL, pr1, 1, 4);
        acc0 += pw0 * f0.x + pw1 * f1.x + pw2 * f2.x + pw3 * f3.x;
        acc1 += pw0 * f0.y + pw1 * f1.y + pw2 * f2.y + pw3 * f3.y;

        // ---- extension pts 4..7: needed iff some group lacks saturation
        // within its first 4 points (bit 4g+1 = lane1's ck1 = cumsum(pt3)) ----
        if ((mb & 0x22222222u) != 0x22222222u) {
            const float pw4 = __shfl_sync(FULL, pr0, 2, 4);
            const float pw5 = __shfl_sync(FULL, pr1, 2, 4);
            const float pw6 = __shfl_sync(FULL, pr0, 3, 4);
            const float pw7 = __shfl_sync(FULL, pr1, 3, 4);
            float2 f4 = __ldcs(reinterpret_cast<const float2*>(fraw + (p0 + 4) * F + 2 * sg));
            float2 f5 = __ldcs(reinterpret_cast<const float2*>(fraw + (p0 + 5) * F + 2 * sg));
            float2 f6 = __ldcs(reinterpret_cast<const float2*>(fraw + (p0 + 6) * F + 2 * sg));
            float2 f7 = __ldcs(reinterpret_cast<const float2*>(fraw + (p0 + 7) * F + 2 * sg));
            acc0 += pw4 * f4.x + pw5 * f5.x + pw6 * f6.x + pw7 * f7.x;
            acc1 += pw4 * f4.y + pw5 * f5.y + pw6 * f6.y + pw7 * f7.y;
        }

        // ---- all groups saturated? (bit 4g+3 = lane3's ck1 = cumsum(pt7)) ----
        if ((mb & 0x88888888u) == 0x88888888u) break;

        base += __shfl_sync(FULL, inc, 3, 4);  // carry raw cumsum (uniform path)
    }

    // ---- depth: reduce over the 4 lanes of the group ----
    depth += __shfl_xor_sync(FULL, depth, 1);
    depth += __shfl_xor_sync(FULL, depth, 2);
    if (valid && sg == 0) depth_out[ray] = depth;

    // ---- features: lane stores feats {2sg, 2sg+1}; fully coalesced ----
    if (valid)
        *reinterpret_cast<float2*>(feat_out + (size_t)ray * F + 2 * sg) =
            make_float2(acc0, acc1);
}

extern "C" void kernel_launch(void* const* d_in, const int* in_sizes, int n_in,
                              void* d_out, int out_size)
{
    const float* dens = (const float*)d_in[0];  // (B,H,W,P,1)
    const float* feat = (const float*)d_in[1];  // (B,H,W,P,F)
    const float* len  = (const float*)d_in[2];  // (B,H,W,P)

    const int R = in_sizes[2] / P;              // number of rays

    float* depth_out = (float*)d_out;           // (B,H,W) flattened
    float* feat_out  = depth_out + R;           // (B,H,W,F) flattened

    const int rays_per_block = WARPS_PER_BLOCK * RAYS_PER_WARP;
    const int blocks = (R + rays_per_block - 1) / rays_per_block;
    raymarch_kernel<<<blocks, THREADS>>>(dens, feat, len, depth_out, feat_out, R);
}

// round 12
// speedup vs baseline: 9.0218x; 1.0436x over previous
#include <cuda_runtime.h>
#include <cstdint>

// DepthEmissionRaymarcher: B=2,H=192,W=320,P=128,F=8
// R11: DRAM-efficiency-bound model (R7/R8 both = 52MB @ ~3.5TB/s effective).
// 8 rays/warp, 4-lane groups, 2 pts/lane. Front-batch only what is ALWAYS
// needed (dens, len, feature pair 0 — pts 0/1 always have nonzero prob);
// feature pairs 1..3 are per-group predicated loads after the scan, so
// unneeded 32B point-sectors are never requested (P(pair1)=0.5, P(pair2)=4%).
// Post-saturation probs are exactly 0 -> skipping is bit-exact.

static constexpr int P = 128;
static constexpr int F = 8;
static constexpr int WARPS_PER_BLOCK = 4;
static constexpr int THREADS = WARPS_PER_BLOCK * 32;
static constexpr int RAYS_PER_WARP = 8;

__global__ __launch_bounds__(THREADS)
void raymarch_kernel(const float* __restrict__ dens,
                     const float* __restrict__ feat,
                     const float* __restrict__ len,
                     float* __restrict__ depth_out,
                     float* __restrict__ feat_out,
                     int R)
{
    const unsigned FULL = 0xffffffffu;
    const int lane = threadIdx.x & 31;
    const int warp = threadIdx.x >> 5;
    const int g  = lane >> 2;        // ray-group within warp (0..7)
    const int sg = lane & 3;         // sub-lane: covers points 2sg, 2sg+1

    const int warp_ray0 = (blockIdx.x * WARPS_PER_BLOCK + warp) * RAYS_PER_WARP;
    if (warp_ray0 >= R) return;      // warp-uniform exit

    int ray = warp_ray0 + g;
    const bool valid = ray < R;
    if (!valid) ray = R - 1;         // safe addresses; writes predicated

    const float* draw = dens + (size_t)ray * P;
    const float* lraw = len  + (size_t)ray * P;
    const float* fraw = feat + (size_t)ray * P * F;

    float base = 0.0f;               // raw cumsum before current chunk
    float depth = 0.0f;
    float acc0 = 0.0f, acc1 = 0.0f;  // feature accum: indices 2sg, 2sg+1

    #pragma unroll 1
    for (int p0 = 0; p0 < P; p0 += 8) {
        const int pl = p0 + 2 * sg;  // this lane's first point

        // ---- front-batched loads: only the always-needed bytes ----
        float2 d2 = __ldcs(reinterpret_cast<const float2*>(draw + pl));
        float2 l2 = __ldcs(reinterpret_cast<const float2*>(lraw + pl));
        // feature pair 0 (points p0, p0+1): probs always nonzero
        float2 f0 = __ldcs(reinterpret_cast<const float2*>(fraw + (p0 + 0) * F + 2 * sg));
        float2 f1 = __ldcs(reinterpret_cast<const float2*>(fraw + (p0 + 1) * F + 2 * sg));

        if (pl + 1 == P - 1) d2.y = 1.0f;   // wall=True on furthest sample

        // ---- scan: pair-sum then 2-round inclusive scan over 4 lanes ----
        const float s = d2.x + d2.y;
        float inc = s;
        {
            float v = __shfl_up_sync(FULL, inc, 1, 4);
            if (sg >= 1) inc += v;
            v = __shfl_up_sync(FULL, inc, 2, 4);
            if (sg >= 2) inc += v;
        }
        const float b    = base + (inc - s);      // cumsum before this lane's pts
        const float ckm1 = fminf(b, 1.0f);
        const float ck0  = fminf(b + d2.x, 1.0f);
        const float ck1  = fminf(b + s, 1.0f);
        const float pr0  = ck0 - ckm1;            // exactly 0 past saturation
        const float pr1  = ck1 - ck0;

        depth += pr0 * l2.x + pr1 * l2.y;

        // per-group saturation nibble; npairs = 1-based first saturated lane
        const unsigned mb = __ballot_sync(FULL, ck1 >= 1.0f);
        const unsigned gbits = (mb >> (g * 4)) & 0xFu;
        const int npairs = gbits ? (int)__ffs(gbits) : 4;

        // ---- feature pair 0: broadcast probs from lane 0 of group ----
        {
            const float pwa = __shfl_sync(FULL, pr0, 0, 4);
            const float pwb = __shfl_sync(FULL, pr1, 0, 4);
            acc0 += pwa * f0.x + pwb * f1.x;
            acc1 += pwa * f0.y + pwb * f1.y;
        }

        // ---- pairs 1..3: predicated per group; unrequested sectors never
        // leave DRAM. shfls stay unconditional (all lanes participate). ----
        #pragma unroll
        for (int i = 1; i < 4; i++) {
            const float pwa = __shfl_sync(FULL, pr0, i, 4);
            const float pwb = __shfl_sync(FULL, pr1, i, 4);
            if (i < npairs) {
                float2 fa = __ldcs(reinterpret_cast<const float2*>(fraw + (p0 + 2 * i)     * F + 2 * sg));
                float2 fb = __ldcs(reinterpret_cast<const float2*>(fraw + (p0 + 2 * i + 1) * F + 2 * sg));
                acc0 += pwa * fa.x + pwb * fb.x;
                acc1 += pwa * fa.y + pwb * fb.y;
            }
        }

        // ---- all groups saturated? (bit 4g+3 = lane3's ck1 = cumsum pt7) ----
        if ((mb & 0x88888888u) == 0x88888888u) break;

        base += __shfl_sync(FULL, inc, 3, 4);  // carry raw cumsum
    }

    // ---- depth: reduce over the 4 lanes of the group ----
    depth += __shfl_xor_sync(FULL, depth, 1);
    depth += __shfl_xor_sync(FULL, depth, 2);
    if (valid && sg == 0) depth_out[ray] = depth;

    // ---- features: lane stores feats {2sg, 2sg+1}; fully coalesced ----
    if (valid)
        *reinterpret_cast<float2*>(feat_out + (size_t)ray * F + 2 * sg) =
            make_float2(acc0, acc1);
}

extern "C" void kernel_launch(void* const* d_in, const int* in_sizes, int n_in,
                              void* d_out, int out_size)
{
    const float* dens = (const float*)d_in[0];  // (B,H,W,P,1)
    const float* feat = (const float*)d_in[1];  // (B,H,W,P,F)
    const float* len  = (const float*)d_in[2];  // (B,H,W,P)

    const int R = in_sizes[2] / P;              // number of rays

    float* depth_out = (float*)d_out;           // (B,H,W) flattened
    float* feat_out  = depth_out + R;           // (B,H,W,F) flattened

    const int rays_per_block = WARPS_PER_BLOCK * RAYS_PER_WARP;
    const int blocks = (R + rays_per_block - 1) / rays_per_block;
    raymarch_kernel<<<blocks, THREADS>>>(dens, feat, len, depth_out, feat_out, R);
}